// round 1
// baseline (speedup 1.0000x reference)
#include <cuda_runtime.h>
#include <math.h>

#define SEQ 4096
#define DIM 2048
#define NH 16
#define HD 128
#define WIN 512

// Scratch (device globals: no allocations allowed)
__device__ float g_Q[SEQ*DIM];
__device__ float g_K[SEQ*DIM];
__device__ float g_V[SEQ*DIM];
__device__ float g_O[SEQ*DIM];
__device__ float g_cos[SEQ*64];
__device__ float g_sin[SEQ*64];

// ---------------------------------------------------------------------------
// RoPE table: inv_freq in fp64, angle product in fp32 (matches XLA rounding),
// cos/sin of that fp32 angle evaluated in fp64.
// ---------------------------------------------------------------------------
__global__ void rope_table_kernel() {
    int idx = blockIdx.x * blockDim.x + threadIdx.x;
    if (idx >= SEQ * 64) return;
    int p = idx & 63;
    int s = idx >> 6;
    float inv = (float)(1.0 / pow(10000.0, (double)(2 * p) / 128.0));
    float ang = (float)s * inv;
    g_cos[idx] = (float)cos((double)ang);
    g_sin[idx] = (float)sin((double)ang);
}

// ---------------------------------------------------------------------------
// SGEMM NT: C[M,N] = A[M,K] * B[N,K]^T, all row-major, fp32.
// 128x128 tile, BK=16, 256 threads, 8x8 register tile.
// ---------------------------------------------------------------------------
__global__ void __launch_bounds__(256) sgemm_nt_kernel(
    const float* __restrict__ A, const float* __restrict__ B,
    float* __restrict__ C, int M, int N, int K)
{
    __shared__ float As[16][128];
    __shared__ float Bs[16][128];
    const int tid = threadIdx.x;
    const int tx = tid & 15, ty = tid >> 4;
    const float* Ab = A + (size_t)blockIdx.y * 128 * K;
    const float* Bb = B + (size_t)blockIdx.x * 128 * K;

    float acc[8][8];
#pragma unroll
    for (int i = 0; i < 8; i++)
#pragma unroll
        for (int j = 0; j < 8; j++) acc[i][j] = 0.f;

    for (int k0 = 0; k0 < K; k0 += 16) {
#pragma unroll
        for (int it = 0; it < 2; it++) {
            int id = tid + it * 256;
            int r = id >> 2, c = (id & 3) << 2;
            float4 av = *(const float4*)(Ab + (size_t)r * K + k0 + c);
            As[c + 0][r] = av.x; As[c + 1][r] = av.y;
            As[c + 2][r] = av.z; As[c + 3][r] = av.w;
            float4 bv = *(const float4*)(Bb + (size_t)r * K + k0 + c);
            Bs[c + 0][r] = bv.x; Bs[c + 1][r] = bv.y;
            Bs[c + 2][r] = bv.z; Bs[c + 3][r] = bv.w;
        }
        __syncthreads();
#pragma unroll
        for (int kk = 0; kk < 16; kk++) {
            float a[8], b[8];
            *(float4*)&a[0] = *(const float4*)&As[kk][ty * 8];
            *(float4*)&a[4] = *(const float4*)&As[kk][ty * 8 + 4];
            *(float4*)&b[0] = *(const float4*)&Bs[kk][tx * 8];
            *(float4*)&b[4] = *(const float4*)&Bs[kk][tx * 8 + 4];
#pragma unroll
            for (int i = 0; i < 8; i++)
#pragma unroll
                for (int j = 0; j < 8; j++)
                    acc[i][j] = fmaf(a[i], b[j], acc[i][j]);
        }
        __syncthreads();
    }

    float* Cb = C + (size_t)(blockIdx.y * 128 + ty * 8) * N + blockIdx.x * 128 + tx * 8;
#pragma unroll
    for (int i = 0; i < 8; i++) {
        *(float4*)(Cb + (size_t)i * N) =
            make_float4(acc[i][0], acc[i][1], acc[i][2], acc[i][3]);
        *(float4*)(Cb + (size_t)i * N + 4) =
            make_float4(acc[i][4], acc[i][5], acc[i][6], acc[i][7]);
    }
}

// ---------------------------------------------------------------------------
// RoPE apply (in-place on g_Q and g_K). One thread per (s, h, pair).
// ---------------------------------------------------------------------------
__global__ void rope_apply_kernel() {
    int idx = blockIdx.x * blockDim.x + threadIdx.x;
    if (idx >= SEQ * NH * 64) return;
    int p = idx & 63;
    int h = (idx >> 6) & 15;
    int s = idx >> 10;
    float c = g_cos[(s << 6) + p];
    float sn = g_sin[(s << 6) + p];
    size_t base = (size_t)s * DIM + h * HD + 2 * p;
    float q1 = g_Q[base], q2 = g_Q[base + 1];
    g_Q[base]     = q1 * c - q2 * sn;
    g_Q[base + 1] = q1 * sn + q2 * c;
    float k1 = g_K[base], k2 = g_K[base + 1];
    g_K[base]     = k1 * c - k2 * sn;
    g_K[base + 1] = k1 * sn + k2 * c;
}

// ---------------------------------------------------------------------------
// Sliding-window flash attention.
// One block per (query-block of 64, head). 256 threads.
// smem: Qt[128][68] (K-transposed Q), KV buffer (Kt[128][68] then Vs[64][132]),
//       Ss[64][68] scores/probs, per-row m/l/corr.
// ---------------------------------------------------------------------------
#define ATT_SMEM_FLOATS (8704 + 8704 + 4352 + 192)
#define ATT_SMEM_BYTES  (ATT_SMEM_FLOATS * 4)

__global__ void __launch_bounds__(256) attn_kernel() {
    extern __shared__ float sm[];
    float* Qt   = sm;               // [128][68]  Qt[k][q]
    float* KV   = sm + 8704;        // Kt[k][j] stride 68  OR  Vs[j][d] stride 132
    float* Ss   = sm + 17408;       // [64][68]
    float* mrow = sm + 21760;       // [64]
    float* lrow = mrow + 64;        // [64]
    float* crow = lrow + 64;        // [64]

    const int tid = threadIdx.x;
    const int tx = tid & 15, ty = tid >> 4;
    const int qb = blockIdx.x;
    const int h  = blockIdx.y;
    const int qb64 = qb * 64;
    const float scale = 0.08838834764831845f;  // 1/sqrt(128)

    // Load Q tile transposed + pre-scaled
    {
        int q  = tid >> 2;
        int c0 = (tid & 3) << 5;
        const float* src = g_Q + (size_t)(qb64 + q) * DIM + h * HD + c0;
#pragma unroll
        for (int it = 0; it < 8; it++) {
            float4 v = *(const float4*)(src + it * 4);
            int k = c0 + it * 4;
            Qt[(k + 0) * 68 + q] = v.x * scale;
            Qt[(k + 1) * 68 + q] = v.y * scale;
            Qt[(k + 2) * 68 + q] = v.z * scale;
            Qt[(k + 3) * 68 + q] = v.w * scale;
        }
    }
    if (tid < 64) { mrow[tid] = -INFINITY; lrow[tid] = 0.f; }

    float o[4][8];
#pragma unroll
    for (int i = 0; i < 4; i++)
#pragma unroll
        for (int j = 0; j < 8; j++) o[i][j] = 0.f;

    const int kb_lo = max(0, qb64 - (WIN - 1)) >> 6;

    for (int kb = kb_lo; kb <= qb; kb++) {
        __syncthreads();  // previous PV done (KV reuse) / Qt ready
        // Load K tile transposed into KV (stride 68)
        {
            int j  = tid >> 2;
            int c0 = (tid & 3) << 5;
            const float* src = g_K + (size_t)(kb * 64 + j) * DIM + h * HD + c0;
#pragma unroll
            for (int it = 0; it < 8; it++) {
                float4 v = *(const float4*)(src + it * 4);
                int k = c0 + it * 4;
                KV[(k + 0) * 68 + j] = v.x;
                KV[(k + 1) * 68 + j] = v.y;
                KV[(k + 2) * 68 + j] = v.z;
                KV[(k + 3) * 68 + j] = v.w;
            }
        }
        __syncthreads();

        // S = (scaled Q) K^T : each thread computes a 4x4 tile of S[64][64]
        float s4[4][4];
#pragma unroll
        for (int i = 0; i < 4; i++)
#pragma unroll
            for (int j = 0; j < 4; j++) s4[i][j] = 0.f;
        for (int k = 0; k < 128; k++) {
            float4 a = *(const float4*)&Qt[k * 68 + ty * 4];
            float4 b = *(const float4*)&KV[k * 68 + tx * 4];
            float av[4] = {a.x, a.y, a.z, a.w};
            float bv[4] = {b.x, b.y, b.z, b.w};
#pragma unroll
            for (int i = 0; i < 4; i++)
#pragma unroll
                for (int j = 0; j < 4; j++)
                    s4[i][j] = fmaf(av[i], bv[j], s4[i][j]);
        }
#pragma unroll
        for (int i = 0; i < 4; i++)
            *(float4*)&Ss[(ty * 4 + i) * 68 + tx * 4] =
                make_float4(s4[i][0], s4[i][1], s4[i][2], s4[i][3]);
        __syncthreads();

        // Softmax (threads 0..63) overlapped with V-tile load (threads 64..255)
        if (tid < 64) {
            const int q  = tid;
            const int qi = qb64 + q;
            const int jlo = max(qi - (WIN - 1) - kb * 64, 0);
            const int jhi = min(qi - kb * 64, 63);
            float mold = mrow[q];
            float mnew = mold;
            for (int j = jlo; j <= jhi; j++)
                mnew = fmaxf(mnew, Ss[q * 68 + j]);
            float corr = (mnew == -INFINITY) ? 1.f : expf(mold - mnew);
            float sum = 0.f;
            for (int j = 0; j < 64; j++) {
                float p = 0.f;
                if (j >= jlo && j <= jhi)
                    p = expf(Ss[q * 68 + j] - mnew);
                Ss[q * 68 + j] = p;
                sum += p;
            }
            lrow[q] = lrow[q] * corr + sum;
            crow[q] = corr;
            mrow[q] = mnew;
        } else {
            int id = tid - 64;
            const float* src = g_V + (size_t)(kb * 64) * DIM + h * HD;
            for (int v = id; v < 2048; v += 192) {   // 2048 float4s = 64x128
                int j  = v >> 5;
                int dd = (v & 31) << 2;
                *(float4*)&KV[j * 132 + dd] =
                    *(const float4*)(src + (size_t)j * DIM + dd);
            }
        }
        __syncthreads();

        // Rescale accumulators and accumulate P @ V
        float cr[4];
#pragma unroll
        for (int i = 0; i < 4; i++) cr[i] = crow[ty * 4 + i];
#pragma unroll
        for (int i = 0; i < 4; i++)
#pragma unroll
            for (int j = 0; j < 8; j++) o[i][j] *= cr[i];
        for (int j = 0; j < 64; j++) {
            float4 v0 = *(const float4*)&KV[j * 132 + tx * 8];
            float4 v1 = *(const float4*)&KV[j * 132 + tx * 8 + 4];
#pragma unroll
            for (int i = 0; i < 4; i++) {
                float p = Ss[(ty * 4 + i) * 68 + j];
                o[i][0] = fmaf(p, v0.x, o[i][0]);
                o[i][1] = fmaf(p, v0.y, o[i][1]);
                o[i][2] = fmaf(p, v0.z, o[i][2]);
                o[i][3] = fmaf(p, v0.w, o[i][3]);
                o[i][4] = fmaf(p, v1.x, o[i][4]);
                o[i][5] = fmaf(p, v1.y, o[i][5]);
                o[i][6] = fmaf(p, v1.z, o[i][6]);
                o[i][7] = fmaf(p, v1.w, o[i][7]);
            }
        }
    }

    // Normalize and write out (lrow/crow writes precede the last pre-PV sync)
#pragma unroll
    for (int i = 0; i < 4; i++) {
        float inv = 1.f / lrow[ty * 4 + i];
        float* dst = g_O + (size_t)(qb64 + ty * 4 + i) * DIM + h * HD + tx * 8;
        *(float4*)dst =
            make_float4(o[i][0] * inv, o[i][1] * inv, o[i][2] * inv, o[i][3] * inv);
        *(float4*)(dst + 4) =
            make_float4(o[i][4] * inv, o[i][5] * inv, o[i][6] * inv, o[i][7] * inv);
    }
}

// ---------------------------------------------------------------------------
// Launch
// ---------------------------------------------------------------------------
extern "C" void kernel_launch(void* const* d_in, const int* in_sizes, int n_in,
                              void* d_out, int out_size) {
    const float* x  = (const float*)d_in[0];
    const float* Wq = (const float*)d_in[1];
    const float* Wk = (const float*)d_in[2];
    const float* Wv = (const float*)d_in[3];
    const float* Wo = (const float*)d_in[4];
    float* out = (float*)d_out;

    float *Q, *K, *V, *O;
    cudaGetSymbolAddress((void**)&Q, g_Q);
    cudaGetSymbolAddress((void**)&K, g_K);
    cudaGetSymbolAddress((void**)&V, g_V);
    cudaGetSymbolAddress((void**)&O, g_O);

    rope_table_kernel<<<(SEQ * 64 + 255) / 256, 256>>>();

    dim3 gg(DIM / 128, SEQ / 128);
    sgemm_nt_kernel<<<gg, 256>>>(x, Wq, Q, SEQ, DIM, DIM);
    sgemm_nt_kernel<<<gg, 256>>>(x, Wk, K, SEQ, DIM, DIM);
    sgemm_nt_kernel<<<gg, 256>>>(x, Wv, V, SEQ, DIM, DIM);

    rope_apply_kernel<<<(SEQ * NH * 64 + 255) / 256, 256>>>();

    cudaFuncSetAttribute(attn_kernel,
                         cudaFuncAttributeMaxDynamicSharedMemorySize,
                         ATT_SMEM_BYTES);
    attn_kernel<<<dim3(SEQ / 64, NH), 256, ATT_SMEM_BYTES>>>();

    sgemm_nt_kernel<<<gg, 256>>>(O, Wo, out, SEQ, DIM, DIM);
}

// round 13
// speedup vs baseline: 1.8842x; 1.8842x over previous
#include <cuda_runtime.h>
#include <cuda_bf16.h>
#include <stdint.h>
#include <cstdint>
#include <math.h>

#define SEQ 4096
#define DIM 2048
#define NH 16
#define HD 128
#define WIN 512

// Scratch (device globals: no allocations allowed)
__device__ float g_Q[SEQ*DIM];
__device__ float g_K[SEQ*DIM];
__device__ float g_V[SEQ*DIM];
__device__ float g_O[SEQ*DIM];
__device__ float g_cos[SEQ*64];
__device__ float g_sin[SEQ*64];
__device__ __nv_bfloat16 g_xhi[SEQ*DIM];
__device__ __nv_bfloat16 g_xlo[SEQ*DIM];
__device__ __nv_bfloat16 g_whi[DIM*DIM];
__device__ __nv_bfloat16 g_wlo[DIM*DIM];

// ===========================================================================
// PTX helpers — ONLY non-arch-specific (sm_80+ baseline) instructions.
// tcgen05/TMEM are 'a'-suffix features; this harness targets compute_103.
// ===========================================================================
__device__ __forceinline__ uint32_t smem_to_u32(const void* p) {
    uint32_t a;
    asm("{ .reg .u64 t; cvta.to.shared.u64 t, %1; cvt.u32.u64 %0, t; }"
        : "=r"(a) : "l"(p));
    return a;
}

__device__ __forceinline__ void ldmx4(uint32_t* r, uint32_t addr) {
    asm volatile("ldmatrix.sync.aligned.m8n8.x4.shared.b16 {%0,%1,%2,%3}, [%4];"
                 : "=r"(r[0]), "=r"(r[1]), "=r"(r[2]), "=r"(r[3]) : "r"(addr));
}

__device__ __forceinline__ void mma16816(float* d, const uint32_t* a, const uint32_t* b) {
    asm volatile("mma.sync.aligned.m16n8k16.row.col.f32.bf16.bf16.f32 "
                 "{%0,%1,%2,%3}, {%4,%5,%6,%7}, {%8,%9}, {%0,%1,%2,%3};"
                 : "+f"(d[0]), "+f"(d[1]), "+f"(d[2]), "+f"(d[3])
                 : "r"(a[0]), "r"(a[1]), "r"(a[2]), "r"(a[3]), "r"(b[0]), "r"(b[1]));
}

__device__ __forceinline__ void cp16(uint32_t saddr, const void* gptr) {
    asm volatile("cp.async.cg.shared.global [%0], [%1], 16;"
                 :: "r"(saddr), "l"(gptr) : "memory");
}

__device__ __forceinline__ void cp_commit() {
    asm volatile("cp.async.commit_group;" ::: "memory");
}

__device__ __forceinline__ void cp_wait0() {
    asm volatile("cp.async.wait_group 0;" ::: "memory");
}

// ===========================================================================
// Split fp32 -> bf16 hi/lo
// ===========================================================================
__global__ void split_kernel(const float* __restrict__ src,
                             __nv_bfloat16* __restrict__ hi,
                             __nv_bfloat16* __restrict__ lo, int n) {
    int i = blockIdx.x * blockDim.x + threadIdx.x;
    if (i >= n) return;
    float v = src[i];
    __nv_bfloat16 h = __float2bfloat16(v);
    hi[i] = h;
    lo[i] = __float2bfloat16(v - __bfloat162float(h));
}

// ===========================================================================
// mma.sync bf16x3 GEMM NT: C[M,N] = A[M,K]*B[N,K]^T, fp32 accumulate.
// CTA 128x128, BK=32, 8 warps (4x2), warp tile 32x64.
// smem tiles padded to stride 40 bf16 (80B) -> conflict-free ldmatrix.
// Double-buffered stages filled via cp.async.
// ===========================================================================
#define GK 2048
#define BK 32
#define NCHUNK (GK / BK)          // 64
#define TS 40                     // bf16 stride per row
#define TILE_B (128 * TS * 2)     // 10240 bytes per tile
#define STAGE_B (4 * TILE_B)      // Ah, Al, Bh, Bl
#define GEMM_SMEM (2 * STAGE_B)   // 81920

extern __shared__ char sm_g[];

__device__ __forceinline__ void cp_tile(uint32_t stile,
                                        const __nv_bfloat16* __restrict__ g,
                                        int row0, int k0) {
    int t = threadIdx.x;
#pragma unroll
    for (int j = 0; j < 2; j++) {
        int idx = t + j * 256;            // 0..511
        int r = idx >> 2, c = idx & 3;    // 128 rows x 4 x 16B
        cp16(stile + r * 80 + c * 16,
             g + (size_t)(row0 + r) * GK + k0 + c * 8);
    }
}

__global__ void __launch_bounds__(256)
gemm_bf16x3_kernel(const __nv_bfloat16* __restrict__ Ah,
                   const __nv_bfloat16* __restrict__ Al,
                   const __nv_bfloat16* __restrict__ Bh,
                   const __nv_bfloat16* __restrict__ Bl,
                   float* __restrict__ C, int N) {
    const uint32_t sb = smem_to_u32(sm_g);
    const int tid = threadIdx.x;
    const int wid = tid >> 5;
    const int lane = tid & 31;
    const int warp_m = wid & 3;       // 4-way M split (32 rows each)
    const int warp_n = wid >> 2;      // 2-way N split (64 cols each)
    const int bm = blockIdx.y, bn = blockIdx.x;
    const int arow = bm * 128, brow = bn * 128;
    const int quad = lane >> 3, rin = lane & 7;

    float acc[2][8][4];
#pragma unroll
    for (int mt = 0; mt < 2; mt++)
#pragma unroll
        for (int nt = 0; nt < 8; nt++)
#pragma unroll
            for (int i = 0; i < 4; i++) acc[mt][nt][i] = 0.f;

    // Preload stage 0
    cp_tile(sb,              Ah, arow, 0);
    cp_tile(sb + TILE_B,     Al, arow, 0);
    cp_tile(sb + 2 * TILE_B, Bh, brow, 0);
    cp_tile(sb + 3 * TILE_B, Bl, brow, 0);
    cp_commit();
    cp_wait0();
    __syncthreads();

    for (int c = 0; c < NCHUNK; c++) {
        const uint32_t st = sb + (c & 1) * STAGE_B;
        if (c + 1 < NCHUNK) {
            const uint32_t st2 = sb + ((c + 1) & 1) * STAGE_B;
            const int k0 = (c + 1) * BK;
            cp_tile(st2,              Ah, arow, k0);
            cp_tile(st2 + TILE_B,     Al, arow, k0);
            cp_tile(st2 + 2 * TILE_B, Bh, brow, k0);
            cp_tile(st2 + 3 * TILE_B, Bl, brow, k0);
            cp_commit();
        }

#pragma unroll
        for (int ks = 0; ks < 2; ks++) {
            uint32_t ahf[2][4], alf[2][4], bhf[8][2], blf[8][2];
            // A fragments: x4 = {m0..15 x k0..15} per mtile
#pragma unroll
            for (int mt = 0; mt < 2; mt++) {
                uint32_t ra = st
                    + (warp_m * 32 + mt * 16 + (quad & 1) * 8 + rin) * 80
                    + (ks * 16 + (quad >> 1) * 8) * 2;
                ldmx4(ahf[mt], ra);
                ldmx4(alf[mt], ra + TILE_B);
            }
            // B fragments: each x4 covers 2 n-tiles (16 n rows x k16)
#pragma unroll
            for (int p = 0; p < 4; p++) {
                uint32_t rb = st + 2 * TILE_B
                    + (warp_n * 64 + p * 16 + (quad >> 1) * 8 + rin) * 80
                    + (ks * 16 + (quad & 1) * 8) * 2;
                uint32_t r4[4];
                ldmx4(r4, rb);
                bhf[2 * p][0] = r4[0]; bhf[2 * p][1] = r4[1];
                bhf[2 * p + 1][0] = r4[2]; bhf[2 * p + 1][1] = r4[3];
                ldmx4(r4, rb + TILE_B);
                blf[2 * p][0] = r4[0]; blf[2 * p][1] = r4[1];
                blf[2 * p + 1][0] = r4[2]; blf[2 * p + 1][1] = r4[3];
            }
#pragma unroll
            for (int mt = 0; mt < 2; mt++)
#pragma unroll
                for (int nt = 0; nt < 8; nt++) {
                    mma16816(acc[mt][nt], ahf[mt], bhf[nt]);
                    mma16816(acc[mt][nt], ahf[mt], blf[nt]);
                    mma16816(acc[mt][nt], alf[mt], bhf[nt]);
                }
        }

        if (c + 1 < NCHUNK) cp_wait0();
        __syncthreads();
    }

    // Epilogue: d0,d1 -> row lane/4, cols (lane%4)*2..+1; d2,d3 -> row+8
#pragma unroll
    for (int mt = 0; mt < 2; mt++) {
        int grow = arow + warp_m * 32 + mt * 16 + (lane >> 2);
#pragma unroll
        for (int nt = 0; nt < 8; nt++) {
            int gcol = bn * 128 + warp_n * 64 + nt * 8 + (lane & 3) * 2;
            *(float2*)(C + (size_t)grow * N + gcol) =
                make_float2(acc[mt][nt][0], acc[mt][nt][1]);
            *(float2*)(C + (size_t)(grow + 8) * N + gcol) =
                make_float2(acc[mt][nt][2], acc[mt][nt][3]);
        }
    }
}

// ===========================================================================
// RoPE table
// ===========================================================================
__global__ void rope_table_kernel() {
    int idx = blockIdx.x * blockDim.x + threadIdx.x;
    if (idx >= SEQ * 64) return;
    int p = idx & 63;
    int s = idx >> 6;
    float inv = (float)(1.0 / pow(10000.0, (double)(2 * p) / 128.0));
    float ang = (float)s * inv;
    g_cos[idx] = (float)cos((double)ang);
    g_sin[idx] = (float)sin((double)ang);
}

// ===========================================================================
// RoPE apply (in-place on g_Q and g_K)
// ===========================================================================
__global__ void rope_apply_kernel() {
    int idx = blockIdx.x * blockDim.x + threadIdx.x;
    if (idx >= SEQ * NH * 64) return;
    int p = idx & 63;
    int h = (idx >> 6) & 15;
    int s = idx >> 10;
    float c = g_cos[(s << 6) + p];
    float sn = g_sin[(s << 6) + p];
    size_t base = (size_t)s * DIM + h * HD + 2 * p;
    float q1 = g_Q[base], q2 = g_Q[base + 1];
    g_Q[base]     = q1 * c - q2 * sn;
    g_Q[base + 1] = q1 * sn + q2 * c;
    float k1 = g_K[base], k2 = g_K[base + 1];
    g_K[base]     = k1 * c - k2 * sn;
    g_K[base + 1] = k1 * sn + k2 * c;
}

// ===========================================================================
// Sliding-window flash attention (unchanged; passing since round 1)
// ===========================================================================
#define ATT_SMEM_FLOATS (8704 + 8704 + 4352 + 192)
#define ATT_SMEM_BYTES  (ATT_SMEM_FLOATS * 4)

extern __shared__ float sm_a[];

__global__ void __launch_bounds__(256) attn_kernel() {
    float* Qt   = sm_a;             // [128][68]  Qt[k][q]
    float* KV   = sm_a + 8704;      // Kt[k][j] stride 68  OR  Vs[j][d] stride 132
    float* Ss   = sm_a + 17408;     // [64][68]
    float* mrow = sm_a + 21760;     // [64]
    float* lrow = mrow + 64;        // [64]
    float* crow = lrow + 64;        // [64]

    const int tid = threadIdx.x;
    const int tx = tid & 15, ty = tid >> 4;
    const int qb = blockIdx.x;
    const int h  = blockIdx.y;
    const int qb64 = qb * 64;
    const float scale = 0.08838834764831845f;  // 1/sqrt(128)

    {
        int q  = tid >> 2;
        int c0 = (tid & 3) << 5;
        const float* src = g_Q + (size_t)(qb64 + q) * DIM + h * HD + c0;
#pragma unroll
        for (int it = 0; it < 8; it++) {
            float4 v = *(const float4*)(src + it * 4);
            int k = c0 + it * 4;
            Qt[(k + 0) * 68 + q] = v.x * scale;
            Qt[(k + 1) * 68 + q] = v.y * scale;
            Qt[(k + 2) * 68 + q] = v.z * scale;
            Qt[(k + 3) * 68 + q] = v.w * scale;
        }
    }
    if (tid < 64) { mrow[tid] = -INFINITY; lrow[tid] = 0.f; }

    float o[4][8];
#pragma unroll
    for (int i = 0; i < 4; i++)
#pragma unroll
        for (int j = 0; j < 8; j++) o[i][j] = 0.f;

    const int kb_lo = max(0, qb64 - (WIN - 1)) >> 6;

    for (int kb = kb_lo; kb <= qb; kb++) {
        __syncthreads();
        {
            int j  = tid >> 2;
            int c0 = (tid & 3) << 5;
            const float* src = g_K + (size_t)(kb * 64 + j) * DIM + h * HD + c0;
#pragma unroll
            for (int it = 0; it < 8; it++) {
                float4 v = *(const float4*)(src + it * 4);
                int k = c0 + it * 4;
                KV[(k + 0) * 68 + j] = v.x;
                KV[(k + 1) * 68 + j] = v.y;
                KV[(k + 2) * 68 + j] = v.z;
                KV[(k + 3) * 68 + j] = v.w;
            }
        }
        __syncthreads();

        float s4[4][4];
#pragma unroll
        for (int i = 0; i < 4; i++)
#pragma unroll
            for (int j = 0; j < 4; j++) s4[i][j] = 0.f;
        for (int k = 0; k < 128; k++) {
            float4 a = *(const float4*)&Qt[k * 68 + ty * 4];
            float4 b = *(const float4*)&KV[k * 68 + tx * 4];
            float av[4] = {a.x, a.y, a.z, a.w};
            float bv[4] = {b.x, b.y, b.z, b.w};
#pragma unroll
            for (int i = 0; i < 4; i++)
#pragma unroll
                for (int j = 0; j < 4; j++)
                    s4[i][j] = fmaf(av[i], bv[j], s4[i][j]);
        }
#pragma unroll
        for (int i = 0; i < 4; i++)
            *(float4*)&Ss[(ty * 4 + i) * 68 + tx * 4] =
                make_float4(s4[i][0], s4[i][1], s4[i][2], s4[i][3]);
        __syncthreads();

        if (tid < 64) {
            const int q  = tid;
            const int qi = qb64 + q;
            const int jlo = max(qi - (WIN - 1) - kb * 64, 0);
            const int jhi = min(qi - kb * 64, 63);
            float mold = mrow[q];
            float mnew = mold;
            for (int j = jlo; j <= jhi; j++)
                mnew = fmaxf(mnew, Ss[q * 68 + j]);
            float corr = (mnew == -INFINITY) ? 1.f : expf(mold - mnew);
            float sum = 0.f;
            for (int j = 0; j < 64; j++) {
                float p = 0.f;
                if (j >= jlo && j <= jhi)
                    p = expf(Ss[q * 68 + j] - mnew);
                Ss[q * 68 + j] = p;
                sum += p;
            }
            lrow[q] = lrow[q] * corr + sum;
            crow[q] = corr;
            mrow[q] = mnew;
        } else {
            int id = tid - 64;
            const float* src = g_V + (size_t)(kb * 64) * DIM + h * HD;
            for (int v = id; v < 2048; v += 192) {
                int j  = v >> 5;
                int dd = (v & 31) << 2;
                *(float4*)&KV[j * 132 + dd] =
                    *(const float4*)(src + (size_t)j * DIM + dd);
            }
        }
        __syncthreads();

        float cr[4];
#pragma unroll
        for (int i = 0; i < 4; i++) cr[i] = crow[ty * 4 + i];
#pragma unroll
        for (int i = 0; i < 4; i++)
#pragma unroll
            for (int j = 0; j < 8; j++) o[i][j] *= cr[i];
        for (int j = 0; j < 64; j++) {
            float4 v0 = *(const float4*)&KV[j * 132 + tx * 8];
            float4 v1 = *(const float4*)&KV[j * 132 + tx * 8 + 4];
#pragma unroll
            for (int i = 0; i < 4; i++) {
                float p = Ss[(ty * 4 + i) * 68 + j];
                o[i][0] = fmaf(p, v0.x, o[i][0]);
                o[i][1] = fmaf(p, v0.y, o[i][1]);
                o[i][2] = fmaf(p, v0.z, o[i][2]);
                o[i][3] = fmaf(p, v0.w, o[i][3]);
                o[i][4] = fmaf(p, v1.x, o[i][4]);
                o[i][5] = fmaf(p, v1.y, o[i][5]);
                o[i][6] = fmaf(p, v1.z, o[i][6]);
                o[i][7] = fmaf(p, v1.w, o[i][7]);
            }
        }
    }

#pragma unroll
    for (int i = 0; i < 4; i++) {
        float inv = 1.f / lrow[ty * 4 + i];
        float* dst = g_O + (size_t)(qb64 + ty * 4 + i) * DIM + h * HD + tx * 8;
        *(float4*)dst =
            make_float4(o[i][0] * inv, o[i][1] * inv, o[i][2] * inv, o[i][3] * inv);
        *(float4*)(dst + 4) =
            make_float4(o[i][4] * inv, o[i][5] * inv, o[i][6] * inv, o[i][7] * inv);
    }
}

// ===========================================================================
// Launch
// ===========================================================================
extern "C" void kernel_launch(void* const* d_in, const int* in_sizes, int n_in,
                              void* d_out, int out_size) {
    const float* x  = (const float*)d_in[0];
    const float* Wq = (const float*)d_in[1];
    const float* Wk = (const float*)d_in[2];
    const float* Wv = (const float*)d_in[3];
    const float* Wo = (const float*)d_in[4];
    float* out = (float*)d_out;

    float *Q, *K, *V, *O;
    cudaGetSymbolAddress((void**)&Q, g_Q);
    cudaGetSymbolAddress((void**)&K, g_K);
    cudaGetSymbolAddress((void**)&V, g_V);
    cudaGetSymbolAddress((void**)&O, g_O);
    __nv_bfloat16 *xhi, *xlo, *whi, *wlo;
    cudaGetSymbolAddress((void**)&xhi, g_xhi);
    cudaGetSymbolAddress((void**)&xlo, g_xlo);
    cudaGetSymbolAddress((void**)&whi, g_whi);
    cudaGetSymbolAddress((void**)&wlo, g_wlo);

    cudaFuncSetAttribute(gemm_bf16x3_kernel,
                         cudaFuncAttributeMaxDynamicSharedMemorySize, GEMM_SMEM);
    cudaFuncSetAttribute(attn_kernel,
                         cudaFuncAttributeMaxDynamicSharedMemorySize,
                         ATT_SMEM_BYTES);

    const int NX = SEQ * DIM, NW = DIM * DIM;
    dim3 gemm_grid(DIM / 128, SEQ / 128);

    rope_table_kernel<<<(SEQ * 64 + 255) / 256, 256>>>();

    split_kernel<<<(NX + 255) / 256, 256>>>(x, xhi, xlo, NX);

    split_kernel<<<(NW + 255) / 256, 256>>>(Wq, whi, wlo, NW);
    gemm_bf16x3_kernel<<<gemm_grid, 256, GEMM_SMEM>>>(xhi, xlo, whi, wlo, Q, DIM);

    split_kernel<<<(NW + 255) / 256, 256>>>(Wk, whi, wlo, NW);
    gemm_bf16x3_kernel<<<gemm_grid, 256, GEMM_SMEM>>>(xhi, xlo, whi, wlo, K, DIM);

    split_kernel<<<(NW + 255) / 256, 256>>>(Wv, whi, wlo, NW);
    gemm_bf16x3_kernel<<<gemm_grid, 256, GEMM_SMEM>>>(xhi, xlo, whi, wlo, V, DIM);

    rope_apply_kernel<<<(SEQ * NH * 64 + 255) / 256, 256>>>();

    attn_kernel<<<dim3(SEQ / 64, NH), 256, ATT_SMEM_BYTES>>>();

    split_kernel<<<(NX + 255) / 256, 256>>>(O, xhi, xlo, NX);
    split_kernel<<<(NW + 255) / 256, 256>>>(Wo, whi, wlo, NW);
    gemm_bf16x3_kernel<<<gemm_grid, 256, GEMM_SMEM>>>(xhi, xlo, whi, wlo, out, DIM);
}